// round 1
// baseline (speedup 1.0000x reference)
#include <cuda_runtime.h>
#include <float.h>

#define NB 16
#define NC 80
#define NH 256
#define NW 256
#define HW (NH*NW)
#define CHW (NC*HW)
#define TOPK 100
#define NBINS 4096
#define REFCAP 262144
#define TILE_H 8
#define THREADS 256
#define BLK3 64
#define SHCAP 4096

// Scratch (static device globals; no allocations allowed)
__device__ float    g_cand_val[NB][CHW];
__device__ int      g_cand_idx[NB][CHW];
__device__ int      g_counts[NB];
__device__ int      g_refcount[NB];
__device__ unsigned g_hist[NB][NBINS];
__device__ int      g_thresh[NB];
__device__ float    g_ref_val[NB][REFCAP];
__device__ int      g_ref_idx[NB][REFCAP];

__device__ __forceinline__ int binOf(float v) {
    int b = (int)(v * (float)NBINS);
    b = b < 0 ? 0 : b;
    return b > (NBINS - 1) ? (NBINS - 1) : b;
}

// ---------------- K0: clear scratch counters/histogram ----------------
__global__ void k0_clear() {
    int i = blockIdx.x * blockDim.x + threadIdx.x;
    if (i < NB * NBINS) ((unsigned*)g_hist)[i] = 0u;
    if (i < NB) { g_counts[i] = 0; g_refcount[i] = 0; }
}

// ---------------- K1: 3x3 max-pool peak detect + candidate collect + histogram ----
__global__ void __launch_bounds__(THREADS) k1_peaks(const float* __restrict__ hm) {
    const int blocksPerPlane = NH / TILE_H;
    const int bc = blockIdx.x / blocksPerPlane;
    const int ht = blockIdx.x % blocksPerPlane;
    const int h0 = ht * TILE_H;
    const int t  = threadIdx.x;      // column index 0..255
    const int b  = bc / NC;
    const int c  = bc % NC;
    const float* plane = hm + (size_t)bc * HW;

    __shared__ float smax[TILE_H][NW];   // vertical maxes per output row
    __shared__ int   sscan[THREADS];
    __shared__ int   sbase;

    // Load this column's 10 rows (with -inf vertical halo) into registers.
    float rows[TILE_H + 2];
    #pragma unroll
    for (int s = 0; s < TILE_H + 2; s++) {
        int h = h0 - 1 + s;
        rows[s] = (h >= 0 && h < NH) ? plane[h * NW + t] : -FLT_MAX;
    }
    #pragma unroll
    for (int r = 0; r < TILE_H; r++) {
        smax[r][t] = fmaxf(fmaxf(rows[r], rows[r + 1]), rows[r + 2]);
    }
    __syncthreads();

    float cv[TILE_H];
    int   ci[TILE_H];
    int n = 0;
    #pragma unroll
    for (int r = 0; r < TILE_H; r++) {
        float m = smax[r][t];
        if (t > 0)      m = fmaxf(m, smax[r][t - 1]);
        if (t < NW - 1) m = fmaxf(m, smax[r][t + 1]);
        float v = rows[r + 1];
        if (v == m) {   // peak: equals its 3x3 window max (window includes self)
            cv[n] = v;
            ci[n] = c * HW + (h0 + r) * NW + t;
            n++;
        }
    }

    // Histogram (distributed REDs; hottest bin sees only ~1.3k ops)
    for (int j = 0; j < n; j++)
        atomicAdd(&g_hist[b][binOf(cv[j])], 1u);

    // Block-level aggregation: inclusive scan of per-thread counts, 1 atomic/block.
    sscan[t] = n;
    __syncthreads();
    for (int off = 1; off < THREADS; off <<= 1) {
        int add = (t >= off) ? sscan[t - off] : 0;
        __syncthreads();
        sscan[t] += add;
        __syncthreads();
    }
    if (t == 0) sbase = atomicAdd(&g_counts[b], sscan[THREADS - 1]);
    __syncthreads();
    int base = sbase + sscan[t] - n;
    for (int j = 0; j < n; j++) {
        g_cand_val[b][base + j] = cv[j];
        g_cand_idx[b][base + j] = ci[j];
    }
}

// ---------------- K2: per-batch threshold bin from histogram suffix counts ----
__global__ void k2_thresh() {
    const int b = blockIdx.x;
    const int t = threadIdx.x;               // 256 threads, 16 bins each
    const int CHUNK = NBINS / THREADS;       // 16
    __shared__ int S[THREADS];
    __shared__ int R[THREADS];
    const unsigned* hist = g_hist[b];

    int sum = 0;
    #pragma unroll
    for (int j = 0; j < CHUNK; j++) sum += (int)hist[t * CHUNK + j];
    S[t] = sum;
    __syncthreads();
    // suffix scan: S[t] = sum over chunks >= t
    for (int off = 1; off < THREADS; off <<= 1) {
        int add = (t + off < THREADS) ? S[t + off] : 0;
        __syncthreads();
        S[t] += add;
        __syncthreads();
    }
    // Within chunk: find max bin whose suffix count >= TOPK
    int acc = (t + 1 < THREADS) ? S[t + 1] : 0;
    int bestLocal = -1;
    for (int j = CHUNK - 1; j >= 0; j--) {
        int bin = t * CHUNK + j;
        acc += (int)hist[bin];
        if (acc >= TOPK) { bestLocal = bin; break; }
    }
    __syncthreads();
    R[t] = bestLocal;
    __syncthreads();
    for (int off = THREADS / 2; off > 0; off >>= 1) {
        if (t < off) R[t] = max(R[t], R[t + off]);
        __syncthreads();
    }
    if (t == 0) g_thresh[b] = max(R[0], 0);
}

// ---------------- K3: compact candidates >= threshold bin ----------------
__global__ void k3_refine() {
    const int b   = blockIdx.x / BLK3;
    const int sub = blockIdx.x % BLK3;
    const int count = min(g_counts[b], CHW);
    const int thr = g_thresh[b];
    const int lane = threadIdx.x & 31;

    for (int i = sub * THREADS + threadIdx.x; ; i += BLK3 * THREADS) {
        bool active = (i < count);
        if (!__ballot_sync(0xffffffffu, active)) break;
        float v = 0.f; int idx = 0; bool match = false;
        if (active) {
            v = g_cand_val[b][i];
            if (binOf(v) >= thr) { match = true; idx = g_cand_idx[b][i]; }
        }
        unsigned m = __ballot_sync(0xffffffffu, match);
        if (m) {
            int leader = __ffs(m) - 1;
            int base = 0;
            if (lane == leader) base = atomicAdd(&g_refcount[b], __popc(m));
            base = __shfl_sync(0xffffffffu, base, leader);
            if (match) {
                int pos = base + __popc(m & ((1u << lane) - 1u));
                if (pos < REFCAP) { g_ref_val[b][pos] = v; g_ref_idx[b][pos] = idx; }
            }
        }
    }
}

// ---------------- K4: per-batch sorted top-100 + gather + output ----------------
__global__ void __launch_bounds__(THREADS) k4_out(const float* __restrict__ offset,
                                                  const float* __restrict__ wh,
                                                  float* __restrict__ out) {
    const int b = blockIdx.x;
    const int t = threadIdx.x;
    __shared__ float sv[SHCAP];
    __shared__ int   si[SHCAP];
    __shared__ float rv[THREADS];
    __shared__ int   ri[THREADS];
    __shared__ int   rp[THREADS];
    __shared__ float topv[TOPK];
    __shared__ int   topi[TOPK];

    const int n2 = min(g_refcount[b], REFCAP);
    const bool useShared = (n2 <= SHCAP);

    if (useShared) {
        for (int i = t; i < SHCAP; i += THREADS) {
            sv[i] = (i < n2) ? g_ref_val[b][i] : -FLT_MAX;
            si[i] = (i < n2) ? g_ref_idx[b][i] : 0x7fffffff;
        }
    }
    __syncthreads();

    for (int r = 0; r < TOPK; r++) {
        float bv = -FLT_MAX; int bi = 0x7fffffff; int bp = -1;
        if (useShared) {
            for (int i = t; i < SHCAP; i += THREADS) {
                float v = sv[i]; int id = si[i];
                if (v > bv || (v == bv && id < bi)) { bv = v; bi = id; bp = i; }
            }
        } else {
            for (int i = t; i < n2; i += THREADS) {
                float v = g_ref_val[b][i]; int id = g_ref_idx[b][i];
                if (v > bv || (v == bv && id < bi)) { bv = v; bi = id; bp = i; }
            }
        }
        rv[t] = bv; ri[t] = bi; rp[t] = bp;
        __syncthreads();
        for (int off = THREADS / 2; off > 0; off >>= 1) {
            if (t < off) {
                float v2 = rv[t + off]; int i2 = ri[t + off];
                if (v2 > rv[t] || (v2 == rv[t] && i2 < ri[t])) {
                    rv[t] = v2; ri[t] = i2; rp[t] = rp[t + off];
                }
            }
            __syncthreads();
        }
        if (t == 0) {
            topv[r] = rv[0]; topi[r] = ri[0];
            int p = rp[0];
            if (p >= 0) {
                if (useShared) sv[p] = -FLT_MAX;
                else g_ref_val[b][p] = -FLT_MAX;
            }
        }
        __syncthreads();   // also makes thread0's global write visible block-wide
    }

    if (t < TOPK) {
        float score = topv[t];
        int idx = topi[t];
        if (idx == 0x7fffffff) { idx = 0; score = 0.f; }   // fewer than K peaks (unreachable here)
        int cls = idx / HW;
        int sp  = idx % HW;
        int y = sp / NW, x = sp % NW;
        const float* offp = offset + (size_t)b * 2 * HW;
        const float* whp  = wh     + (size_t)b * 2 * HW;
        float ox = offp[sp];
        float oy = offp[HW + sp];
        float bw = whp[sp];
        float bh = whp[HW + sp];
        float cx = (float)x + ox;
        float cy = (float)y + oy;
        float hw2 = bw * 0.5f, hh2 = bh * 0.5f;
        bool mask = score > 0.01f;

        float* ids_o = out;
        float* sc_o  = out + NB * TOPK;
        float* bb_o  = out + 2 * NB * TOPK;
        int o = b * TOPK + t;
        ids_o[o] = mask ? (float)cls : -1.f;
        sc_o[o]  = mask ? score : -1.f;
        // mask applied BEFORE the *SCALE multiply (masked bbox = -1*4 = -4)
        float x1 = mask ? (cx - hw2) : -1.f;
        float y1 = mask ? (cy - hh2) : -1.f;
        float x2 = mask ? (cx + hw2) : -1.f;
        float y2 = mask ? (cy + hh2) : -1.f;
        bb_o[o * 4 + 0] = x1 * 4.0f;
        bb_o[o * 4 + 1] = y1 * 4.0f;
        bb_o[o * 4 + 2] = x2 * 4.0f;
        bb_o[o * 4 + 3] = y2 * 4.0f;
    }
}

extern "C" void kernel_launch(void* const* d_in, const int* in_sizes, int n_in,
                              void* d_out, int out_size) {
    const float* hm     = (const float*)d_in[0];   // (16,80,256,256)
    const float* offset = (const float*)d_in[1];   // (16,2,256,256)
    const float* wh     = (const float*)d_in[2];   // (16,2,256,256)
    float* out = (float*)d_out;                    // 9600 floats: ids | scores | bboxes

    k0_clear<<<(NB * NBINS + THREADS - 1) / THREADS, THREADS>>>();
    k1_peaks<<<NB * NC * (NH / TILE_H), THREADS>>>(hm);
    k2_thresh<<<NB, THREADS>>>();
    k3_refine<<<NB * BLK3, THREADS>>>();
    k4_out<<<NB, THREADS>>>(offset, wh, out);
}

// round 6
// speedup vs baseline: 1.3760x; 1.3760x over previous
#include <cuda_runtime.h>
#include <float.h>

#define NB 16
#define NC 80
#define NH 256
#define NW 256
#define HW (NH*NW)
#define CHW (NC*HW)
#define TOPK 100
#define NBINS 4096
#define TILE_H 16
#define THREADS 256
#define SEGCAP 8192
#define CUT 0.98f
#define FB_BLK 64
#define SORT_N 512

// ---------------- static scratch ----------------
__device__ unsigned g_hist[NB][NBINS];
__device__ int      g_segcount[NB*NC];
__device__ float    g_seg_val[NB*NC][SEGCAP];
__device__ int      g_seg_idx[NB*NC][SEGCAP];
__device__ int      g_thresh[NB];
__device__ int      g_fallback[NB];
__device__ int      g_refcount[NB];
__device__ float    g_ref_val[NB][CHW];   // big only for (never-taken) fallback
__device__ int      g_ref_idx[NB][CHW];

__device__ __forceinline__ int binOf(float v) {
    int b = (int)((v - CUT) * ((float)NBINS / (1.0f - CUT)));
    b = b < 0 ? 0 : b;
    return b > (NBINS - 1) ? (NBINS - 1) : b;
}

// ---------------- K0: clear counters ----------------
__global__ void k0_clear() {
    int i = blockIdx.x * blockDim.x + threadIdx.x;
    if (i < NB * NBINS) ((unsigned*)g_hist)[i] = 0u;
    if (i < NB * NC) g_segcount[i] = 0;
    if (i < NB) { g_refcount[i] = 0; g_fallback[i] = 0; }
}

// ---------------- K1: streaming peak detect + hist + rare candidate store ----
__global__ void __launch_bounds__(THREADS) k1_peaks(const float* __restrict__ hm) {
    const int blocksPerPlane = NH / TILE_H;          // 16
    const int bc = blockIdx.x / blocksPerPlane;
    const int ht = blockIdx.x % blocksPerPlane;
    const int h0 = ht * TILE_H;
    const int t  = threadIdx.x;                      // column 0..255
    const int b  = bc / NC;
    const int c  = bc % NC;
    const int lane = t & 31;
    const float* plane = hm + (size_t)bc * HW;

    __shared__ float smax[TILE_H][NW];

    float rows[TILE_H + 2];
    #pragma unroll
    for (int s = 0; s < TILE_H + 2; s++) {
        int h = h0 - 1 + s;
        rows[s] = (h >= 0 && h < NH) ? plane[h * NW + t] : -FLT_MAX;
    }
    #pragma unroll
    for (int r = 0; r < TILE_H; r++)
        smax[r][t] = fmaxf(fmaxf(rows[r], rows[r + 1]), rows[r + 2]);
    __syncthreads();

    #pragma unroll
    for (int r = 0; r < TILE_H; r++) {
        float m = smax[r][t];
        if (t > 0)      m = fmaxf(m, smax[r][t - 1]);
        if (t < NW - 1) m = fmaxf(m, smax[r][t + 1]);
        float v = rows[r + 1];
        bool cand = (v == m) && (v >= CUT);          // peak AND above cut
        unsigned mk = __ballot_sync(0xffffffffu, cand);
        if (mk) {
            if (cand) atomicAdd(&g_hist[b][binOf(v)], 1u);
            int leader = __ffs(mk) - 1;
            int base = 0;
            if (lane == leader) base = atomicAdd(&g_segcount[bc], __popc(mk));
            base = __shfl_sync(0xffffffffu, base, leader);
            if (cand) {
                int pos = base + __popc(mk & ((1u << lane) - 1u));
                if (pos < SEGCAP) {
                    g_seg_val[bc][pos] = v;
                    g_seg_idx[bc][pos] = c * HW + (h0 + r) * NW + t;
                } else {
                    g_fallback[b] = 1;               // overflow -> exact brute force
                }
            }
        }
    }
}

// ---------------- K2: threshold bin from histogram suffix counts ----------------
__global__ void k2_thresh() {
    const int b = blockIdx.x;
    const int t = threadIdx.x;
    const int CHUNK = NBINS / THREADS;               // 16
    __shared__ int S[THREADS];
    __shared__ int R[THREADS];
    const unsigned* hist = g_hist[b];

    int sum = 0;
    #pragma unroll
    for (int j = 0; j < CHUNK; j++) sum += (int)hist[t * CHUNK + j];
    S[t] = sum;
    __syncthreads();
    for (int off = 1; off < THREADS; off <<= 1) {
        int add = (t + off < THREADS) ? S[t + off] : 0;
        __syncthreads();
        S[t] += add;
        __syncthreads();
    }
    int acc = (t + 1 < THREADS) ? S[t + 1] : 0;
    int bestLocal = -1;
    for (int j = CHUNK - 1; j >= 0; j--) {
        int bin = t * CHUNK + j;
        acc += (int)hist[bin];
        if (acc >= TOPK) { bestLocal = bin; break; }
    }
    __syncthreads();
    R[t] = bestLocal;
    int total = S[0];
    __syncthreads();
    for (int off = THREADS / 2; off > 0; off >>= 1) {
        if (t < off) R[t] = max(R[t], R[t + off]);
        __syncthreads();
    }
    if (t == 0) {
        g_thresh[b] = max(R[0], 0);
        if (total < TOPK) g_fallback[b] = 1;
    }
}

// ---------------- K3: compact segment candidates >= threshold ----------------
__global__ void __launch_bounds__(THREADS) k3_compact() {
    const int bc = blockIdx.x;
    const int b  = bc / NC;
    if (g_fallback[b]) return;
    const int thr = g_thresh[b];
    const int cnt = min(g_segcount[bc], SEGCAP);
    const int lane = threadIdx.x & 31;
    const int end = (cnt + THREADS - 1) & ~(THREADS - 1);

    for (int i = threadIdx.x; i < end; i += THREADS) {
        bool match = false; float v = 0.f; int idx = 0;
        if (i < cnt) {
            v = g_seg_val[bc][i];
            if (binOf(v) >= thr) { match = true; idx = g_seg_idx[bc][i]; }
        }
        unsigned mk = __ballot_sync(0xffffffffu, match);
        if (mk) {
            int leader = __ffs(mk) - 1;
            int base = 0;
            if (lane == leader) base = atomicAdd(&g_refcount[b], __popc(mk));
            base = __shfl_sync(0xffffffffu, base, leader);
            if (match) {
                int pos = base + __popc(mk & ((1u << lane) - 1u));
                g_ref_val[b][pos] = v;
                g_ref_idx[b][pos] = idx;
            }
        }
    }
}

// ---------------- K3b: exact brute-force fallback (normally no-op) ----------------
__global__ void __launch_bounds__(THREADS) k3b_fallback(const float* __restrict__ hm) {
    const int b   = blockIdx.x / FB_BLK;
    if (!g_fallback[b]) return;
    const int sub = blockIdx.x % FB_BLK;
    const int t = threadIdx.x;
    const int lane = t & 31;

    for (int rc = sub; rc < NC * NH; rc += FB_BLK) {
        const int c = rc / NH;
        const int h = rc % NH;
        const float* plane = hm + ((size_t)b * NC + c) * HW;
        float v = plane[h * NW + t];
        float m = v;
        for (int dh = -1; dh <= 1; dh++) {
            int hh = h + dh;
            if (hh < 0 || hh >= NH) continue;
            for (int dw = -1; dw <= 1; dw++) {
                int ww = t + dw;
                if (ww < 0 || ww >= NW) continue;
                m = fmaxf(m, plane[hh * NW + ww]);
            }
        }
        bool cand = (v == m);                        // ALL peaks, exact
        unsigned mk = __ballot_sync(0xffffffffu, cand);
        if (mk) {
            int leader = __ffs(mk) - 1;
            int base = 0;
            if (lane == leader) base = atomicAdd(&g_refcount[b], __popc(mk));
            base = __shfl_sync(0xffffffffu, base, leader);
            if (cand) {
                int pos = base + __popc(mk & ((1u << lane) - 1u));
                g_ref_val[b][pos] = v;
                g_ref_idx[b][pos] = c * HW + h * NW + t;
            }
        }
    }
}

// ---------------- K4: per-batch top-100 (bitonic) + gather + output ----------------
__device__ __forceinline__ unsigned fkey(float v) {
    unsigned u = __float_as_uint(v);
    return (u & 0x80000000u) ? ~u : (u | 0x80000000u);   // monotone asc mapping
}
__device__ __forceinline__ float fkey_inv(unsigned k) {
    unsigned u = (k & 0x80000000u) ? (k & 0x7fffffffu) : ~k;
    return __uint_as_float(u);
}

__global__ void __launch_bounds__(THREADS) k4_out(const float* __restrict__ offset,
                                                  const float* __restrict__ wh,
                                                  float* __restrict__ out) {
    const int b = blockIdx.x;
    const int t = threadIdx.x;
    const int n2 = min(g_refcount[b], CHW);

    __shared__ unsigned long long keys[SORT_N];
    __shared__ float topv_s[TOPK];
    __shared__ int   topi_s[TOPK];

    float myscore = 0.f;
    int   myidx = 0x7fffffff;

    if (n2 <= SORT_N) {
        // ---- bitonic sort of 512 packed keys, descending ----
        for (int i = t; i < SORT_N; i += THREADS) {
            if (i < n2) {
                float v = g_ref_val[b][i];
                int idx = g_ref_idx[b][i];
                keys[i] = ((unsigned long long)fkey(v) << 32) | (unsigned)(~idx);
            } else {
                keys[i] = 0ull;                        // sorts last
            }
        }
        __syncthreads();
        for (int k = 2; k <= SORT_N; k <<= 1) {
            for (int j = k >> 1; j > 0; j >>= 1) {
                #pragma unroll
                for (int e = 0; e < SORT_N / THREADS; e++) {
                    int i = t + THREADS * e;
                    int l = i ^ j;
                    if (l > i) {
                        bool descBlock = ((i & k) == 0);
                        unsigned long long a = keys[i], bb = keys[l];
                        bool swap = descBlock ? (a < bb) : (a > bb);
                        if (swap) { keys[i] = bb; keys[l] = a; }
                    }
                }
                __syncthreads();
            }
        }
        if (t < TOPK) {
            unsigned long long kk = keys[t];
            if (kk == 0ull) { myscore = 0.f; myidx = 0x7fffffff; }
            else {
                myscore = fkey_inv((unsigned)(kk >> 32));
                myidx   = (int)(~(unsigned)kk);
            }
        }
    } else {
        // ---- iterative exact selection over global (fallback only) ----
        __shared__ float rv[THREADS];
        __shared__ int   ri[THREADS];
        __shared__ int   rp[THREADS];
        for (int r = 0; r < TOPK; r++) {
            float bv = -FLT_MAX; int bi = 0x7fffffff; int bp = -1;
            for (int i = t; i < n2; i += THREADS) {
                float v = g_ref_val[b][i]; int id = g_ref_idx[b][i];
                if (v > bv || (v == bv && id < bi)) { bv = v; bi = id; bp = i; }
            }
            rv[t] = bv; ri[t] = bi; rp[t] = bp;
            __syncthreads();
            for (int off = THREADS / 2; off > 0; off >>= 1) {
                if (t < off) {
                    float v2 = rv[t + off]; int i2 = ri[t + off];
                    if (v2 > rv[t] || (v2 == rv[t] && i2 < ri[t])) {
                        rv[t] = v2; ri[t] = i2; rp[t] = rp[t + off];
                    }
                }
                __syncthreads();
            }
            if (t == 0) {
                topv_s[r] = rv[0]; topi_s[r] = ri[0];
                if (rp[0] >= 0) g_ref_val[b][rp[0]] = -FLT_MAX;
            }
            __syncthreads();
        }
        if (t < TOPK) { myscore = topv_s[t]; myidx = topi_s[t]; }
    }

    // ---- gather + output (layout validated in round 1) ----
    if (t < TOPK) {
        float score = myscore;
        int idx = myidx;
        if (idx == 0x7fffffff) { idx = 0; score = 0.f; }
        int cls = idx / HW;
        int sp  = idx % HW;
        int y = sp / NW, x = sp % NW;
        const float* offp = offset + (size_t)b * 2 * HW;
        const float* whp  = wh     + (size_t)b * 2 * HW;
        float ox = offp[sp];
        float oy = offp[HW + sp];
        float bw = whp[sp];
        float bh = whp[HW + sp];
        float cx = (float)x + ox;
        float cy = (float)y + oy;
        float hw2 = bw * 0.5f, hh2 = bh * 0.5f;
        bool mask = score > 0.01f;

        float* ids_o = out;
        float* sc_o  = out + NB * TOPK;
        float* bb_o  = out + 2 * NB * TOPK;
        int o = b * TOPK + t;
        ids_o[o] = mask ? (float)cls : -1.f;
        sc_o[o]  = mask ? score : -1.f;
        float x1 = mask ? (cx - hw2) : -1.f;
        float y1 = mask ? (cy - hh2) : -1.f;
        float x2 = mask ? (cx + hw2) : -1.f;
        float y2 = mask ? (cy + hh2) : -1.f;
        bb_o[o * 4 + 0] = x1 * 4.0f;
        bb_o[o * 4 + 1] = y1 * 4.0f;
        bb_o[o * 4 + 2] = x2 * 4.0f;
        bb_o[o * 4 + 3] = y2 * 4.0f;
    }
}

extern "C" void kernel_launch(void* const* d_in, const int* in_sizes, int n_in,
                              void* d_out, int out_size) {
    const float* hm     = (const float*)d_in[0];   // (16,80,256,256)
    const float* offset = (const float*)d_in[1];   // (16,2,256,256)
    const float* wh     = (const float*)d_in[2];   // (16,2,256,256)
    float* out = (float*)d_out;

    k0_clear<<<(NB * NBINS + THREADS - 1) / THREADS, THREADS>>>();
    k1_peaks<<<NB * NC * (NH / TILE_H), THREADS>>>(hm);
    k2_thresh<<<NB, THREADS>>>();
    k3_compact<<<NB * NC, THREADS>>>();
    k3b_fallback<<<NB * FB_BLK, THREADS>>>(hm);
    k4_out<<<NB, THREADS>>>(offset, wh, out);
}

// round 8
// speedup vs baseline: 6.2311x; 4.5285x over previous
#include <cuda_runtime.h>
#include <float.h>

#define NB 16
#define NC 80
#define NH 256
#define NW 256
#define HW (NH*NW)
#define CHW (NC*HW)
#define TOPK 100
#define THREADS 256
#define CUT 0.999f
#define SEGCAP 2048
#define NBINS2 2048
#define COLCAP 512

// ---------------- static scratch ----------------
__device__ int   g_segcount[NB*NC];
__device__ int   g_overflow[NB];
__device__ float g_seg_val[NB*NC][SEGCAP];
__device__ int   g_seg_idx[NB*NC][SEGCAP];

__device__ __forceinline__ int binOf(float v) {
    int x = (int)((v - CUT) * ((float)NBINS2 / (1.0f - CUT)));
    x = x < 0 ? 0 : x;
    return x > (NBINS2 - 1) ? (NBINS2 - 1) : x;
}
__device__ __forceinline__ unsigned fkey(float v) {
    unsigned u = __float_as_uint(v);
    return (u & 0x80000000u) ? ~u : (u | 0x80000000u);
}
__device__ __forceinline__ float fkey_inv(unsigned k) {
    unsigned u = (k & 0x80000000u) ? (k & 0x7fffffffu) : ~k;
    return __uint_as_float(u);
}
__device__ __forceinline__ unsigned long long packKey(float v, int idx) {
    return ((unsigned long long)fkey(v) << 32) | (unsigned)(~idx);
}

// ---------------- K0: clear counters ----------------
__global__ void k0_clear() {
    int i = blockIdx.x * blockDim.x + threadIdx.x;
    if (i < NB * NC) g_segcount[i] = 0;
    if (i < NB) g_overflow[i] = 0;
}

// ---------------- K1: streaming scan; rare-path peak test ----------------
__global__ void __launch_bounds__(THREADS) k1_scan(const float* __restrict__ hm) {
    const int bc = blockIdx.x >> 2;          // (b,c) plane
    const int rt = blockIdx.x & 3;           // 64-row tile within plane
    const int b  = bc / NC;
    const int c  = bc % NC;
    const int t  = threadIdx.x;
    const int sx = t & 63;                   // 4-col strip
    const int ry = t >> 6;                   // row group (0..3)
    const float* plane = hm + (size_t)bc * HW;
    const float4* p4 = (const float4*)plane;
    const int row0 = rt * 64 + ry * 16;

    #pragma unroll 8
    for (int r = 0; r < 16; r++) {
        const int row = row0 + r;
        float4 v = __ldg(&p4[row * 64 + sx]);
        float m = fmaxf(fmaxf(v.x, v.y), fmaxf(v.z, v.w));
        if (m >= CUT) {
            float vals[4] = {v.x, v.y, v.z, v.w};
            #pragma unroll
            for (int cc = 0; cc < 4; cc++) {
                float vv = vals[cc];
                if (vv < CUT) continue;
                int col = sx * 4 + cc;
                // 3x3 neighborhood max (window includes self), SAME padding
                float mx = -FLT_MAX;
                for (int dh = -1; dh <= 1; dh++) {
                    int rr = row + dh;
                    if ((unsigned)rr >= NH) continue;
                    for (int dw = -1; dw <= 1; dw++) {
                        int wc = col + dw;
                        if ((unsigned)wc >= NW) continue;
                        mx = fmaxf(mx, plane[rr * NW + wc]);
                    }
                }
                if (vv == mx) {                          // peak
                    int pos = atomicAdd(&g_segcount[bc], 1);
                    if (pos < SEGCAP) {
                        g_seg_val[bc][pos] = vv;
                        g_seg_idx[bc][pos] = c * HW + row * NW + col;
                    } else {
                        g_overflow[b] = 1;
                    }
                }
            }
        }
    }
}

// ---------------- K2: per-batch threshold + top-100 + gather + output ----------
__global__ void __launch_bounds__(THREADS) k2_select(const float* __restrict__ hm,
                                                     const float* __restrict__ offset,
                                                     const float* __restrict__ wh,
                                                     float* __restrict__ out) {
    const int b = blockIdx.x;
    const int t = threadIdx.x;

    __shared__ int      scnt[NC];
    __shared__ unsigned hist[NBINS2];
    __shared__ unsigned long long keys[COLCAP];
    __shared__ int S[THREADS];
    __shared__ int R[THREADS];
    __shared__ unsigned long long rk[THREADS];
    __shared__ int s_n, s_m;

    if (t < NC) scnt[t] = min(g_segcount[b * NC + t], SEGCAP);
    for (int i = t; i < NBINS2; i += THREADS) hist[i] = 0u;
    if (t == 0) s_m = 0;
    __syncthreads();
    if (t == 0) { int n = 0; for (int s = 0; s < NC; s++) n += scnt[s]; s_n = n; }
    __syncthreads();
    const int n = s_n;
    const bool exactHM = (g_overflow[b] != 0) || (n < TOPK);

    float myscore = 0.f;
    int   myidx = 0x7fffffff;

    if (!exactHM) {
        // ---- pass 1: smem histogram over all candidates of this batch ----
        for (int s = 0; s < NC; s++) {
            const float* sv = g_seg_val[b * NC + s];
            const int cnt = scnt[s];
            for (int i = t; i < cnt; i += THREADS)
                atomicAdd(&hist[binOf(sv[i])], 1u);
        }
        __syncthreads();
        // ---- threshold: max bin with suffix count >= TOPK ----
        const int CH = NBINS2 / THREADS;   // 8
        int sum = 0;
        #pragma unroll
        for (int j = 0; j < CH; j++) sum += (int)hist[t * CH + j];
        S[t] = sum;
        __syncthreads();
        for (int off = 1; off < THREADS; off <<= 1) {
            int add = (t + off < THREADS) ? S[t + off] : 0;
            __syncthreads();
            S[t] += add;
            __syncthreads();
        }
        int acc = (t + 1 < THREADS) ? S[t + 1] : 0;
        int best = -1;
        for (int j = CH - 1; j >= 0; j--) {
            int bin = t * CH + j;
            acc += (int)hist[bin];
            if (acc >= TOPK) { best = bin; break; }
        }
        R[t] = best;
        __syncthreads();
        for (int off = THREADS / 2; off > 0; off >>= 1) {
            if (t < off) R[t] = max(R[t], R[t + off]);
            __syncthreads();
        }
        const int thr = max(R[0], 0);
        __syncthreads();
        // ---- pass 2: collect survivors ----
        for (int s = 0; s < NC; s++) {
            const float* sv = g_seg_val[b * NC + s];
            const int*   si = g_seg_idx[b * NC + s];
            const int cnt = scnt[s];
            for (int i = t; i < cnt; i += THREADS) {
                float v = sv[i];
                if (binOf(v) >= thr) {
                    int pos = atomicAdd(&s_m, 1);
                    if (pos < COLCAP) keys[pos] = packKey(v, si[i]);
                }
            }
        }
        __syncthreads();
        const int m = s_m;

        if (m <= COLCAP) {
            // ---- bitonic sort of 512 packed keys, descending ----
            for (int i = t; i < COLCAP; i += THREADS)
                if (i >= m) keys[i] = 0ull;
            __syncthreads();
            for (int k = 2; k <= COLCAP; k <<= 1) {
                for (int j = k >> 1; j > 0; j >>= 1) {
                    #pragma unroll
                    for (int e = 0; e < COLCAP / THREADS; e++) {
                        int i = t + THREADS * e;
                        int l = i ^ j;
                        if (l > i) {
                            bool desc = ((i & k) == 0);
                            unsigned long long a = keys[i], bb = keys[l];
                            if (desc ? (a < bb) : (a > bb)) { keys[i] = bb; keys[l] = a; }
                        }
                    }
                    __syncthreads();
                }
            }
            if (t < TOPK) {
                unsigned long long kk = keys[t];
                if (kk) { myscore = fkey_inv((unsigned)(kk >> 32)); myidx = (int)(~(unsigned)kk); }
            }
        } else {
            // ---- Tier B (never taken): exact iterative over segments ----
            unsigned long long prev = 0xFFFFFFFFFFFFFFFFull;
            for (int r = 0; r < TOPK; r++) {
                unsigned long long bk = 0ull;
                for (int s = 0; s < NC; s++) {
                    const float* sv = g_seg_val[b * NC + s];
                    const int*   si = g_seg_idx[b * NC + s];
                    const int cnt = scnt[s];
                    for (int i = t; i < cnt; i += THREADS) {
                        unsigned long long kk = packKey(sv[i], si[i]);
                        if (kk < prev && kk > bk) bk = kk;
                    }
                }
                rk[t] = bk;
                __syncthreads();
                for (int off = THREADS / 2; off > 0; off >>= 1) {
                    if (t < off) rk[t] = max(rk[t], rk[t + off]);
                    __syncthreads();
                }
                unsigned long long top = rk[0];
                if (t == r && top) { myscore = fkey_inv((unsigned)(top >> 32)); myidx = (int)(~(unsigned)top); }
                prev = top;
                __syncthreads();
            }
        }
    } else {
        // ---- Tier C (never taken): exact iterative over full heatmap ----
        const float* hmb = hm + (size_t)b * CHW;
        unsigned long long prev = 0xFFFFFFFFFFFFFFFFull;
        for (int r = 0; r < TOPK; r++) {
            unsigned long long bk = 0ull;
            for (int cell = t; cell < CHW; cell += THREADS) {
                float v = hmb[cell];
                unsigned long long kk = packKey(v, cell);
                if (kk >= prev || kk <= bk) continue;
                int sp = cell % HW;
                int row = sp / NW, col = sp % NW;
                const float* plane = hmb + (cell / HW) * HW;
                float mx = -FLT_MAX;
                for (int dh = -1; dh <= 1; dh++) {
                    int rr = row + dh;
                    if ((unsigned)rr >= NH) continue;
                    for (int dw = -1; dw <= 1; dw++) {
                        int wc = col + dw;
                        if ((unsigned)wc >= NW) continue;
                        mx = fmaxf(mx, plane[rr * NW + wc]);
                    }
                }
                if (v == mx) bk = kk;
            }
            rk[t] = bk;
            __syncthreads();
            for (int off = THREADS / 2; off > 0; off >>= 1) {
                if (t < off) rk[t] = max(rk[t], rk[t + off]);
                __syncthreads();
            }
            unsigned long long top = rk[0];
            if (t == r && top) { myscore = fkey_inv((unsigned)(top >> 32)); myidx = (int)(~(unsigned)top); }
            prev = top;
            __syncthreads();
        }
    }

    // ---- gather + output (layout validated: rel_err 0) ----
    if (t < TOPK) {
        float score = myscore;
        int idx = myidx;
        if (idx == 0x7fffffff) { idx = 0; score = 0.f; }
        int cls = idx / HW;
        int sp  = idx % HW;
        int y = sp / NW, x = sp % NW;
        const float* offp = offset + (size_t)b * 2 * HW;
        const float* whp  = wh     + (size_t)b * 2 * HW;
        float ox = offp[sp];
        float oy = offp[HW + sp];
        float bw = whp[sp];
        float bh = whp[HW + sp];
        float cx = (float)x + ox;
        float cy = (float)y + oy;
        float hw2 = bw * 0.5f, hh2 = bh * 0.5f;
        bool mask = score > 0.01f;

        float* ids_o = out;
        float* sc_o  = out + NB * TOPK;
        float* bb_o  = out + 2 * NB * TOPK;
        int o = b * TOPK + t;
        ids_o[o] = mask ? (float)cls : -1.f;
        sc_o[o]  = mask ? score : -1.f;
        float x1 = mask ? (cx - hw2) : -1.f;
        float y1 = mask ? (cy - hh2) : -1.f;
        float x2 = mask ? (cx + hw2) : -1.f;
        float y2 = mask ? (cy + hh2) : -1.f;
        bb_o[o * 4 + 0] = x1 * 4.0f;
        bb_o[o * 4 + 1] = y1 * 4.0f;
        bb_o[o * 4 + 2] = x2 * 4.0f;
        bb_o[o * 4 + 3] = y2 * 4.0f;
    }
}

extern "C" void kernel_launch(void* const* d_in, const int* in_sizes, int n_in,
                              void* d_out, int out_size) {
    const float* hm     = (const float*)d_in[0];   // (16,80,256,256)
    const float* offset = (const float*)d_in[1];   // (16,2,256,256)
    const float* wh     = (const float*)d_in[2];   // (16,2,256,256)
    float* out = (float*)d_out;

    k0_clear<<<(NB * NC + THREADS - 1) / THREADS, THREADS>>>();
    k1_scan<<<NB * NC * 4, THREADS>>>(hm);
    k2_select<<<NB, THREADS>>>(hm, offset, wh, out);
}

// round 11
// speedup vs baseline: 7.7725x; 1.2474x over previous
#include <cuda_runtime.h>
#include <float.h>

#define NB 16
#define NC 80
#define NH 256
#define NW 256
#define HW (NH*NW)
#define CHW (NC*HW)
#define TOPK 100
#define THREADS 256
#define CUT 0.999f
#define CAP 16384
#define NBINS2 2048
#define COLCAP 512

// ---------------- static scratch (zero-initialized at module load) ----------------
__device__ int                g_count[NB];
__device__ int                g_overflow[NB];
__device__ unsigned long long g_cand[NB][CAP];

__device__ __forceinline__ int binOf(float v) {
    int x = (int)((v - CUT) * ((float)NBINS2 / (1.0f - CUT)));
    x = x < 0 ? 0 : x;
    return x > (NBINS2 - 1) ? (NBINS2 - 1) : x;
}
__device__ __forceinline__ unsigned fkey(float v) {
    unsigned u = __float_as_uint(v);
    return (u & 0x80000000u) ? ~u : (u | 0x80000000u);
}
__device__ __forceinline__ float fkey_inv(unsigned k) {
    unsigned u = (k & 0x80000000u) ? (k & 0x7fffffffu) : ~k;
    return __uint_as_float(u);
}
__device__ __forceinline__ unsigned long long packKey(float v, int idx) {
    return ((unsigned long long)fkey(v) << 32) | (unsigned)(~idx);
}

// ---------------- K1: streaming scan, branch-free load phase ----------------
__global__ void __launch_bounds__(THREADS) k1_scan(const float* __restrict__ hm) {
    const int bc = blockIdx.x >> 2;          // (b,c) plane
    const int rt = blockIdx.x & 3;           // 64-row tile
    const int b  = bc / NC;
    const int c  = bc % NC;
    const int t  = threadIdx.x;
    const int sx = t & 63;                   // 4-col strip
    const int ry = t >> 6;                   // row group 0..3
    const float* plane = hm + (size_t)bc * HW;
    const float4* p4 = (const float4*)plane;
    const int row0 = rt * 64 + ry * 16;

    // Phase 1: 16 independent LDG.128, no branches -> batched MLP
    float rowmax[16];
    #pragma unroll
    for (int r = 0; r < 16; r++) {
        float4 v = __ldg(&p4[(row0 + r) * 64 + sx]);
        rowmax[r] = fmaxf(fmaxf(v.x, v.y), fmaxf(v.z, v.w));
    }
    float tmax = rowmax[0];
    #pragma unroll
    for (int r = 1; r < 16; r++) tmax = fmaxf(tmax, rowmax[r]);
    if (tmax < CUT) return;                  // 99.6% of threads exit here

    // Phase 2 (rare): per-row peak test with L1-hot reloads
    #pragma unroll 1
    for (int r = 0; r < 16; r++) {
        if (rowmax[r] < CUT) continue;
        const int row = row0 + r;
        float4 v = p4[row * 64 + sx];
        float vals[4] = {v.x, v.y, v.z, v.w};
        #pragma unroll 1
        for (int cc = 0; cc < 4; cc++) {
            float vv = vals[cc];
            if (vv < CUT) continue;
            int col = sx * 4 + cc;
            float mx = -FLT_MAX;
            for (int dh = -1; dh <= 1; dh++) {
                int rr = row + dh;
                if ((unsigned)rr >= NH) continue;
                for (int dw = -1; dw <= 1; dw++) {
                    int wc = col + dw;
                    if ((unsigned)wc >= NW) continue;
                    mx = fmaxf(mx, plane[rr * NW + wc]);
                }
            }
            if (vv == mx) {                  // 3x3 peak (window includes self)
                int pos = atomicAdd(&g_count[b], 1);
                if (pos < CAP) g_cand[b][pos] = packKey(vv, c * HW + row * NW + col);
                else g_overflow[b] = 1;
            }
        }
    }
}

// ---------------- K2: per-batch threshold + top-100 + gather + output ----------
__global__ void __launch_bounds__(THREADS) k2_select(const float* __restrict__ hm,
                                                     const float* __restrict__ offset,
                                                     const float* __restrict__ wh,
                                                     float* __restrict__ out) {
    const int b = blockIdx.x;
    const int t = threadIdx.x;

    __shared__ unsigned hist[NBINS2];
    __shared__ unsigned long long keys[COLCAP];
    __shared__ int S[THREADS];
    __shared__ int R[THREADS];
    __shared__ unsigned long long rk[THREADS];
    __shared__ int s_m;

    const int n = min(g_count[b], CAP);
    const bool exactHM = (g_overflow[b] != 0) || (n < TOPK);
    const unsigned long long* cand = g_cand[b];

    for (int i = t; i < NBINS2; i += THREADS) hist[i] = 0u;
    if (t == 0) s_m = 0;
    __syncthreads();

    float myscore = 0.f;
    int   myidx = 0x7fffffff;

    if (!exactHM) {
        // ---- pass 1: smem histogram ----
        for (int i = t; i < n; i += THREADS)
            atomicAdd(&hist[binOf(fkey_inv((unsigned)(cand[i] >> 32)))], 1u);
        __syncthreads();
        // ---- threshold: max bin with suffix count >= TOPK ----
        const int CH = NBINS2 / THREADS;     // 8
        int sum = 0;
        #pragma unroll
        for (int j = 0; j < CH; j++) sum += (int)hist[t * CH + j];
        S[t] = sum;
        __syncthreads();
        for (int off = 1; off < THREADS; off <<= 1) {
            int add = (t + off < THREADS) ? S[t + off] : 0;
            __syncthreads();
            S[t] += add;
            __syncthreads();
        }
        int acc = (t + 1 < THREADS) ? S[t + 1] : 0;
        int best = -1;
        for (int j = CH - 1; j >= 0; j--) {
            int bin = t * CH + j;
            acc += (int)hist[bin];
            if (acc >= TOPK) { best = bin; break; }
        }
        R[t] = best;
        __syncthreads();
        for (int off = THREADS / 2; off > 0; off >>= 1) {
            if (t < off) R[t] = max(R[t], R[t + off]);
            __syncthreads();
        }
        const int thr = max(R[0], 0);
        __syncthreads();
        // ---- pass 2: collect survivors ----
        for (int i = t; i < n; i += THREADS) {
            unsigned long long kk = cand[i];
            if (binOf(fkey_inv((unsigned)(kk >> 32))) >= thr) {
                int pos = atomicAdd(&s_m, 1);
                if (pos < COLCAP) keys[pos] = kk;
            }
        }
        __syncthreads();
        const int m = s_m;

        if (m <= COLCAP) {
            // ---- bitonic sort of 512 packed keys, descending ----
            for (int i = t; i < COLCAP; i += THREADS)
                if (i >= m) keys[i] = 0ull;
            __syncthreads();
            for (int k = 2; k <= COLCAP; k <<= 1) {
                for (int j = k >> 1; j > 0; j >>= 1) {
                    #pragma unroll
                    for (int e = 0; e < COLCAP / THREADS; e++) {
                        int i = t + THREADS * e;
                        int l = i ^ j;
                        if (l > i) {
                            bool desc = ((i & k) == 0);
                            unsigned long long a = keys[i], bb = keys[l];
                            if (desc ? (a < bb) : (a > bb)) { keys[i] = bb; keys[l] = a; }
                        }
                    }
                    __syncthreads();
                }
            }
            if (t < TOPK) {
                unsigned long long kk = keys[t];
                if (kk) { myscore = fkey_inv((unsigned)(kk >> 32)); myidx = (int)(~(unsigned)kk); }
            }
        } else {
            // ---- Tier B (never taken): exact iterative over candidates ----
            unsigned long long prev = 0xFFFFFFFFFFFFFFFFull;
            for (int r = 0; r < TOPK; r++) {
                unsigned long long bk = 0ull;
                for (int i = t; i < n; i += THREADS) {
                    unsigned long long kk = cand[i];
                    if (kk < prev && kk > bk) bk = kk;
                }
                rk[t] = bk;
                __syncthreads();
                for (int off = THREADS / 2; off > 0; off >>= 1) {
                    if (t < off) rk[t] = max(rk[t], rk[t + off]);
                    __syncthreads();
                }
                unsigned long long top = rk[0];
                if (t == r && top) { myscore = fkey_inv((unsigned)(top >> 32)); myidx = (int)(~(unsigned)top); }
                prev = top;
                __syncthreads();
            }
        }
    } else {
        // ---- Tier C (never taken): exact iterative over full heatmap ----
        const float* hmb = hm + (size_t)b * CHW;
        unsigned long long prev = 0xFFFFFFFFFFFFFFFFull;
        for (int r = 0; r < TOPK; r++) {
            unsigned long long bk = 0ull;
            for (int cell = t; cell < CHW; cell += THREADS) {
                float v = hmb[cell];
                unsigned long long kk = packKey(v, cell);
                if (kk >= prev || kk <= bk) continue;
                int sp = cell % HW;
                int row = sp / NW, col = sp % NW;
                const float* plane = hmb + (cell / HW) * HW;
                float mx = -FLT_MAX;
                for (int dh = -1; dh <= 1; dh++) {
                    int rr = row + dh;
                    if ((unsigned)rr >= NH) continue;
                    for (int dw = -1; dw <= 1; dw++) {
                        int wc = col + dw;
                        if ((unsigned)wc >= NW) continue;
                        mx = fmaxf(mx, plane[rr * NW + wc]);
                    }
                }
                if (v == mx) bk = kk;
            }
            rk[t] = bk;
            __syncthreads();
            for (int off = THREADS / 2; off > 0; off >>= 1) {
                if (t < off) rk[t] = max(rk[t], rk[t + off]);
                __syncthreads();
            }
            unsigned long long top = rk[0];
            if (t == r && top) { myscore = fkey_inv((unsigned)(top >> 32)); myidx = (int)(~(unsigned)top); }
            prev = top;
            __syncthreads();
        }
    }

    // ---- gather + output (layout validated: rel_err 0) ----
    if (t < TOPK) {
        float score = myscore;
        int idx = myidx;
        if (idx == 0x7fffffff) { idx = 0; score = 0.f; }
        int cls = idx / HW;
        int sp  = idx % HW;
        int y = sp / NW, x = sp % NW;
        const float* offp = offset + (size_t)b * 2 * HW;
        const float* whp  = wh     + (size_t)b * 2 * HW;
        float ox = offp[sp];
        float oy = offp[HW + sp];
        float bw = whp[sp];
        float bh = whp[HW + sp];
        float cx = (float)x + ox;
        float cy = (float)y + oy;
        float hw2 = bw * 0.5f, hh2 = bh * 0.5f;
        bool mask = score > 0.01f;

        float* ids_o = out;
        float* sc_o  = out + NB * TOPK;
        float* bb_o  = out + 2 * NB * TOPK;
        int o = b * TOPK + t;
        ids_o[o] = mask ? (float)cls : -1.f;
        sc_o[o]  = mask ? score : -1.f;
        float x1 = mask ? (cx - hw2) : -1.f;
        float y1 = mask ? (cy - hh2) : -1.f;
        float x2 = mask ? (cx + hw2) : -1.f;
        float y2 = mask ? (cy + hh2) : -1.f;
        bb_o[o * 4 + 0] = x1 * 4.0f;
        bb_o[o * 4 + 1] = y1 * 4.0f;
        bb_o[o * 4 + 2] = x2 * 4.0f;
        bb_o[o * 4 + 3] = y2 * 4.0f;
    }

    // ---- reset counters for the next graph replay ----
    if (t == 0) { g_count[b] = 0; g_overflow[b] = 0; }
}

extern "C" void kernel_launch(void* const* d_in, const int* in_sizes, int n_in,
                              void* d_out, int out_size) {
    const float* hm     = (const float*)d_in[0];   // (16,80,256,256)
    const float* offset = (const float*)d_in[1];   // (16,2,256,256)
    const float* wh     = (const float*)d_in[2];   // (16,2,256,256)
    float* out = (float*)d_out;

    k1_scan<<<NB * NC * 4, THREADS>>>(hm);
    k2_select<<<NB, THREADS>>>(hm, offset, wh, out);
}

// round 12
// speedup vs baseline: 11.5386x; 1.4845x over previous
#include <cuda_runtime.h>
#include <float.h>

#define NB 16
#define NC 80
#define NH 256
#define NW 256
#define HW (NH*NW)
#define CHW (NC*HW)
#define TOPK 100
#define THREADS 256
#define CUT 0.9998f
#define CAP 16384
#define SORT_N 2048

// ---------------- static scratch (zero-initialized at module load) ----------------
__device__ int                g_count[NB];
__device__ int                g_overflow[NB];
__device__ unsigned long long g_cand[NB][CAP];

__device__ __forceinline__ unsigned fkey(float v) {
    unsigned u = __float_as_uint(v);
    return (u & 0x80000000u) ? ~u : (u | 0x80000000u);
}
__device__ __forceinline__ float fkey_inv(unsigned k) {
    unsigned u = (k & 0x80000000u) ? (k & 0x7fffffffu) : ~k;
    return __uint_as_float(u);
}
__device__ __forceinline__ unsigned long long packKey(float v, int idx) {
    return ((unsigned long long)fkey(v) << 32) | (unsigned)(~idx);
}
__device__ __forceinline__ float max4(float4 v) {
    return fmaxf(fmaxf(v.x, v.y), fmaxf(v.z, v.w));
}

// ---------------- K1: streaming scan, minimal-register load phase ----------------
__global__ void __launch_bounds__(THREADS) k1_scan(const float* __restrict__ hm) {
    const int bc = blockIdx.x >> 2;          // (b,c) plane
    const int rt = blockIdx.x & 3;           // 64-row tile
    const int b  = bc / NC;
    const int c  = bc % NC;
    const int t  = threadIdx.x;
    const int sx = t & 63;                   // 4-col strip
    const int ry = t >> 6;                   // row group 0..3
    const float* plane = hm + (size_t)bc * HW;
    const float4* p4 = (const float4*)plane;
    const int row0 = rt * 64 + ry * 16;
    const float4* base = p4 + row0 * 64 + sx;

    // Phase 1: 16 streaming LDG.128 with only 4 running maxes (values in [0,1))
    float m0 = 0.f, m1 = 0.f, m2 = 0.f, m3 = 0.f;
    #pragma unroll
    for (int r = 0; r < 16; r += 4) {
        float4 a = __ldcs(base + (r + 0) * 64);
        float4 bb = __ldcs(base + (r + 1) * 64);
        float4 cc = __ldcs(base + (r + 2) * 64);
        float4 dd = __ldcs(base + (r + 3) * 64);
        m0 = fmaxf(m0, max4(a));
        m1 = fmaxf(m1, max4(bb));
        m2 = fmaxf(m2, max4(cc));
        m3 = fmaxf(m3, max4(dd));
    }
    if (fmaxf(fmaxf(m0, m1), fmaxf(m2, m3)) < CUT) return;   // ~98.7% exit

    // Phase 2 (rare, ~1.3% of threads): reload rows from cache, peak-test
    #pragma unroll 1
    for (int r = 0; r < 16; r++) {
        const int row = row0 + r;
        float4 v = base[r * 64];
        if (max4(v) < CUT) continue;
        float vals[4] = {v.x, v.y, v.z, v.w};
        #pragma unroll 1
        for (int e = 0; e < 4; e++) {
            float vv = vals[e];
            if (vv < CUT) continue;
            int col = sx * 4 + e;
            float mx = -FLT_MAX;
            for (int dh = -1; dh <= 1; dh++) {
                int rr = row + dh;
                if ((unsigned)rr >= NH) continue;
                for (int dw = -1; dw <= 1; dw++) {
                    int wc = col + dw;
                    if ((unsigned)wc >= NW) continue;
                    mx = fmaxf(mx, plane[rr * NW + wc]);
                }
            }
            if (vv == mx) {                  // 3x3 peak (window includes self)
                int pos = atomicAdd(&g_count[b], 1);
                if (pos < CAP) g_cand[b][pos] = packKey(vv, c * HW + row * NW + col);
                else g_overflow[b] = 1;
            }
        }
    }
}

// ---------------- K2: per-batch top-100 via bitonic sort + gather + output ----
__global__ void __launch_bounds__(THREADS) k2_select(const float* __restrict__ hm,
                                                     const float* __restrict__ offset,
                                                     const float* __restrict__ wh,
                                                     float* __restrict__ out) {
    const int b = blockIdx.x;
    const int t = threadIdx.x;

    __shared__ unsigned long long keys[SORT_N];
    __shared__ unsigned long long rk[THREADS];

    const int n = min(g_count[b], CAP);
    const bool tierC = (g_overflow[b] != 0) || (n < TOPK);
    const unsigned long long* cand = g_cand[b];

    float myscore = 0.f;
    int   myidx = 0x7fffffff;

    if (!tierC && n <= SORT_N) {
        // ---- Tier A: load all candidates, bitonic sort 2048, take top-100 ----
        #pragma unroll
        for (int e = 0; e < SORT_N / THREADS; e++) {
            int i = t + THREADS * e;
            keys[i] = (i < n) ? cand[i] : 0ull;
        }
        __syncthreads();
        for (int k = 2; k <= SORT_N; k <<= 1) {
            for (int j = k >> 1; j > 0; j >>= 1) {
                #pragma unroll
                for (int e = 0; e < SORT_N / THREADS; e++) {
                    int i = t + THREADS * e;
                    int l = i ^ j;
                    if (l > i) {
                        bool desc = ((i & k) == 0);
                        unsigned long long a = keys[i], bb = keys[l];
                        if (desc ? (a < bb) : (a > bb)) { keys[i] = bb; keys[l] = a; }
                    }
                }
                __syncthreads();
            }
        }
        if (t < TOPK) {
            unsigned long long kk = keys[t];
            if (kk) { myscore = fkey_inv((unsigned)(kk >> 32)); myidx = (int)(~(unsigned)kk); }
        }
    } else if (!tierC) {
        // ---- Tier B (never taken): exact iterative selection over candidates ----
        unsigned long long prev = 0xFFFFFFFFFFFFFFFFull;
        for (int r = 0; r < TOPK; r++) {
            unsigned long long bk = 0ull;
            for (int i = t; i < n; i += THREADS) {
                unsigned long long kk = cand[i];
                if (kk < prev && kk > bk) bk = kk;
            }
            rk[t] = bk;
            __syncthreads();
            for (int off = THREADS / 2; off > 0; off >>= 1) {
                if (t < off) rk[t] = max(rk[t], rk[t + off]);
                __syncthreads();
            }
            unsigned long long top = rk[0];
            if (t == r && top) { myscore = fkey_inv((unsigned)(top >> 32)); myidx = (int)(~(unsigned)top); }
            prev = top;
            __syncthreads();
        }
    } else {
        // ---- Tier C (never taken): exact iterative over full heatmap ----
        const float* hmb = hm + (size_t)b * CHW;
        unsigned long long prev = 0xFFFFFFFFFFFFFFFFull;
        for (int r = 0; r < TOPK; r++) {
            unsigned long long bk = 0ull;
            for (int cell = t; cell < CHW; cell += THREADS) {
                float v = hmb[cell];
                unsigned long long kk = packKey(v, cell);
                if (kk >= prev || kk <= bk) continue;
                int sp = cell % HW;
                int row = sp / NW, col = sp % NW;
                const float* plane = hmb + (cell / HW) * HW;
                float mx = -FLT_MAX;
                for (int dh = -1; dh <= 1; dh++) {
                    int rr = row + dh;
                    if ((unsigned)rr >= NH) continue;
                    for (int dw = -1; dw <= 1; dw++) {
                        int wc = col + dw;
                        if ((unsigned)wc >= NW) continue;
                        mx = fmaxf(mx, plane[rr * NW + wc]);
                    }
                }
                if (v == mx) bk = kk;
            }
            rk[t] = bk;
            __syncthreads();
            for (int off = THREADS / 2; off > 0; off >>= 1) {
                if (t < off) rk[t] = max(rk[t], rk[t + off]);
                __syncthreads();
            }
            unsigned long long top = rk[0];
            if (t == r && top) { myscore = fkey_inv((unsigned)(top >> 32)); myidx = (int)(~(unsigned)top); }
            prev = top;
            __syncthreads();
        }
    }

    // ---- gather + output (layout validated: rel_err 0) ----
    if (t < TOPK) {
        float score = myscore;
        int idx = myidx;
        if (idx == 0x7fffffff) { idx = 0; score = 0.f; }
        int cls = idx / HW;
        int sp  = idx % HW;
        int y = sp / NW, x = sp % NW;
        const float* offp = offset + (size_t)b * 2 * HW;
        const float* whp  = wh     + (size_t)b * 2 * HW;
        float ox = offp[sp];
        float oy = offp[HW + sp];
        float bw = whp[sp];
        float bh = whp[HW + sp];
        float cx = (float)x + ox;
        float cy = (float)y + oy;
        float hw2 = bw * 0.5f, hh2 = bh * 0.5f;
        bool mask = score > 0.01f;

        float* ids_o = out;
        float* sc_o  = out + NB * TOPK;
        float* bb_o  = out + 2 * NB * TOPK;
        int o = b * TOPK + t;
        ids_o[o] = mask ? (float)cls : -1.f;
        sc_o[o]  = mask ? score : -1.f;
        float x1 = mask ? (cx - hw2) : -1.f;
        float y1 = mask ? (cy - hh2) : -1.f;
        float x2 = mask ? (cx + hw2) : -1.f;
        float y2 = mask ? (cy + hh2) : -1.f;
        bb_o[o * 4 + 0] = x1 * 4.0f;
        bb_o[o * 4 + 1] = y1 * 4.0f;
        bb_o[o * 4 + 2] = x2 * 4.0f;
        bb_o[o * 4 + 3] = y2 * 4.0f;
    }

    // ---- reset counters for the next graph replay ----
    if (t == 0) { g_count[b] = 0; g_overflow[b] = 0; }
}

extern "C" void kernel_launch(void* const* d_in, const int* in_sizes, int n_in,
                              void* d_out, int out_size) {
    const float* hm     = (const float*)d_in[0];   // (16,80,256,256)
    const float* offset = (const float*)d_in[1];   // (16,2,256,256)
    const float* wh     = (const float*)d_in[2];   // (16,2,256,256)
    float* out = (float*)d_out;

    k1_scan<<<NB * NC * 4, THREADS>>>(hm);
    k2_select<<<NB, THREADS>>>(hm, offset, wh, out);
}

// round 13
// speedup vs baseline: 17.2649x; 1.4963x over previous
#include <cuda_runtime.h>
#include <float.h>

#define NB 16
#define NC 80
#define NH 256
#define NW 256
#define HW (NH*NW)
#define CHW (NC*HW)
#define TOPK 100
#define THREADS 256
#define THREADS2 512
#define CUT 0.99995f
#define CAP 16384
#define SORT_N 512

// ---------------- static scratch (zero-initialized at module load) ----------------
__device__ int                g_count[NB];
__device__ int                g_overflow[NB];
__device__ unsigned long long g_cand[NB][CAP];

__device__ __forceinline__ unsigned fkey(float v) {
    unsigned u = __float_as_uint(v);
    return (u & 0x80000000u) ? ~u : (u | 0x80000000u);
}
__device__ __forceinline__ float fkey_inv(unsigned k) {
    unsigned u = (k & 0x80000000u) ? (k & 0x7fffffffu) : ~k;
    return __uint_as_float(u);
}
__device__ __forceinline__ unsigned long long packKey(float v, int idx) {
    return ((unsigned long long)fkey(v) << 32) | (unsigned)(~idx);
}
__device__ __forceinline__ float max4(float4 v) {
    return fmaxf(fmaxf(v.x, v.y), fmaxf(v.z, v.w));
}

// ---------------- K1: streaming scan, minimal-register load phase ----------------
__global__ void __launch_bounds__(THREADS) k1_scan(const float* __restrict__ hm) {
    const int bc = blockIdx.x >> 2;          // (b,c) plane
    const int rt = blockIdx.x & 3;           // 64-row tile
    const int b  = bc / NC;
    const int c  = bc % NC;
    const int t  = threadIdx.x;
    const int sx = t & 63;                   // 4-col strip
    const int ry = t >> 6;                   // row group 0..3
    const float* plane = hm + (size_t)bc * HW;
    const float4* p4 = (const float4*)plane;
    const int row0 = rt * 64 + ry * 16;
    const float4* base = p4 + row0 * 64 + sx;

    // Phase 1: 16 streaming LDG.128 with only 4 running maxes (values in [0,1))
    float m0 = 0.f, m1 = 0.f, m2 = 0.f, m3 = 0.f;
    #pragma unroll
    for (int r = 0; r < 16; r += 4) {
        float4 a = __ldcs(base + (r + 0) * 64);
        float4 bb = __ldcs(base + (r + 1) * 64);
        float4 cc = __ldcs(base + (r + 2) * 64);
        float4 dd = __ldcs(base + (r + 3) * 64);
        m0 = fmaxf(m0, max4(a));
        m1 = fmaxf(m1, max4(bb));
        m2 = fmaxf(m2, max4(cc));
        m3 = fmaxf(m3, max4(dd));
    }
    if (fmaxf(fmaxf(m0, m1), fmaxf(m2, m3)) < CUT) return;   // ~99.7% exit

    // Phase 2 (rare): reload rows from cache, peak-test
    #pragma unroll 1
    for (int r = 0; r < 16; r++) {
        const int row = row0 + r;
        float4 v = base[r * 64];
        if (max4(v) < CUT) continue;
        float vals[4] = {v.x, v.y, v.z, v.w};
        #pragma unroll 1
        for (int e = 0; e < 4; e++) {
            float vv = vals[e];
            if (vv < CUT) continue;
            int col = sx * 4 + e;
            float mx = -FLT_MAX;
            for (int dh = -1; dh <= 1; dh++) {
                int rr = row + dh;
                if ((unsigned)rr >= NH) continue;
                for (int dw = -1; dw <= 1; dw++) {
                    int wc = col + dw;
                    if ((unsigned)wc >= NW) continue;
                    mx = fmaxf(mx, plane[rr * NW + wc]);
                }
            }
            if (vv == mx) {                  // 3x3 peak (window includes self)
                int pos = atomicAdd(&g_count[b], 1);
                if (pos < CAP) g_cand[b][pos] = packKey(vv, c * HW + row * NW + col);
                else g_overflow[b] = 1;
            }
        }
    }
}

// ---------------- K2: per-batch top-100 via 512-key bitonic + gather + output ----
__global__ void __launch_bounds__(THREADS2) k2_select(const float* __restrict__ hm,
                                                      const float* __restrict__ offset,
                                                      const float* __restrict__ wh,
                                                      float* __restrict__ out) {
    const int b = blockIdx.x;
    const int t = threadIdx.x;

    __shared__ unsigned long long keys[SORT_N];
    __shared__ unsigned long long rk[THREADS2];

    const int n = min(g_count[b], CAP);
    const bool tierC = (g_overflow[b] != 0) || (n < TOPK);
    const unsigned long long* cand = g_cand[b];

    float myscore = 0.f;
    int   myidx = 0x7fffffff;

    if (!tierC && n <= SORT_N) {
        // ---- Tier A: bitonic sort 512 keys with 512 threads (1 slot/thread) ----
        if (t < SORT_N) keys[t] = (t < n) ? cand[t] : 0ull;
        __syncthreads();
        for (int k = 2; k <= SORT_N; k <<= 1) {
            for (int j = k >> 1; j > 0; j >>= 1) {
                int i = t;
                int l = i ^ j;
                if (i < SORT_N && l > i) {
                    bool desc = ((i & k) == 0);
                    unsigned long long a = keys[i], bb = keys[l];
                    if (desc ? (a < bb) : (a > bb)) { keys[i] = bb; keys[l] = a; }
                }
                __syncthreads();
            }
        }
        if (t < TOPK) {
            unsigned long long kk = keys[t];
            if (kk) { myscore = fkey_inv((unsigned)(kk >> 32)); myidx = (int)(~(unsigned)kk); }
        }
    } else if (!tierC) {
        // ---- Tier B (never taken): exact iterative selection over candidates ----
        unsigned long long prev = 0xFFFFFFFFFFFFFFFFull;
        for (int r = 0; r < TOPK; r++) {
            unsigned long long bk = 0ull;
            for (int i = t; i < n; i += THREADS2) {
                unsigned long long kk = cand[i];
                if (kk < prev && kk > bk) bk = kk;
            }
            rk[t] = bk;
            __syncthreads();
            for (int off = THREADS2 / 2; off > 0; off >>= 1) {
                if (t < off) rk[t] = max(rk[t], rk[t + off]);
                __syncthreads();
            }
            unsigned long long top = rk[0];
            if (t == r && top) { myscore = fkey_inv((unsigned)(top >> 32)); myidx = (int)(~(unsigned)top); }
            prev = top;
            __syncthreads();
        }
    } else {
        // ---- Tier C (never taken): exact iterative over full heatmap ----
        const float* hmb = hm + (size_t)b * CHW;
        unsigned long long prev = 0xFFFFFFFFFFFFFFFFull;
        for (int r = 0; r < TOPK; r++) {
            unsigned long long bk = 0ull;
            for (int cell = t; cell < CHW; cell += THREADS2) {
                float v = hmb[cell];
                unsigned long long kk = packKey(v, cell);
                if (kk >= prev || kk <= bk) continue;
                int sp = cell % HW;
                int row = sp / NW, col = sp % NW;
                const float* plane = hmb + (cell / HW) * HW;
                float mx = -FLT_MAX;
                for (int dh = -1; dh <= 1; dh++) {
                    int rr = row + dh;
                    if ((unsigned)rr >= NH) continue;
                    for (int dw = -1; dw <= 1; dw++) {
                        int wc = col + dw;
                        if ((unsigned)wc >= NW) continue;
                        mx = fmaxf(mx, plane[rr * NW + wc]);
                    }
                }
                if (v == mx) bk = kk;
            }
            rk[t] = bk;
            __syncthreads();
            for (int off = THREADS2 / 2; off > 0; off >>= 1) {
                if (t < off) rk[t] = max(rk[t], rk[t + off]);
                __syncthreads();
            }
            unsigned long long top = rk[0];
            if (t == r && top) { myscore = fkey_inv((unsigned)(top >> 32)); myidx = (int)(~(unsigned)top); }
            prev = top;
            __syncthreads();
        }
    }

    // ---- gather + output (layout validated: rel_err 0) ----
    if (t < TOPK) {
        float score = myscore;
        int idx = myidx;
        if (idx == 0x7fffffff) { idx = 0; score = 0.f; }
        int cls = idx / HW;
        int sp  = idx % HW;
        int y = sp / NW, x = sp % NW;
        const float* offp = offset + (size_t)b * 2 * HW;
        const float* whp  = wh     + (size_t)b * 2 * HW;
        float ox = offp[sp];
        float oy = offp[HW + sp];
        float bw = whp[sp];
        float bh = whp[HW + sp];
        float cx = (float)x + ox;
        float cy = (float)y + oy;
        float hw2 = bw * 0.5f, hh2 = bh * 0.5f;
        bool mask = score > 0.01f;

        float* ids_o = out;
        float* sc_o  = out + NB * TOPK;
        float* bb_o  = out + 2 * NB * TOPK;
        int o = b * TOPK + t;
        ids_o[o] = mask ? (float)cls : -1.f;
        sc_o[o]  = mask ? score : -1.f;
        float x1 = mask ? (cx - hw2) : -1.f;
        float y1 = mask ? (cy - hh2) : -1.f;
        float x2 = mask ? (cx + hw2) : -1.f;
        float y2 = mask ? (cy + hh2) : -1.f;
        bb_o[o * 4 + 0] = x1 * 4.0f;
        bb_o[o * 4 + 1] = y1 * 4.0f;
        bb_o[o * 4 + 2] = x2 * 4.0f;
        bb_o[o * 4 + 3] = y2 * 4.0f;
    }

    // ---- reset counters for the next graph replay ----
    if (t == 0) { g_count[b] = 0; g_overflow[b] = 0; }
}

extern "C" void kernel_launch(void* const* d_in, const int* in_sizes, int n_in,
                              void* d_out, int out_size) {
    const float* hm     = (const float*)d_in[0];   // (16,80,256,256)
    const float* offset = (const float*)d_in[1];   // (16,2,256,256)
    const float* wh     = (const float*)d_in[2];   // (16,2,256,256)
    float* out = (float*)d_out;

    k1_scan<<<NB * NC * 4, THREADS>>>(hm);
    k2_select<<<NB, THREADS2>>>(hm, offset, wh, out);
}